// round 8
// baseline (speedup 1.0000x reference)
#include <cuda_runtime.h>
#include <math.h>

#define NB   32
#define NT   512
#define ND   1024
#define NCB  256
#define ROWS (NB*NT)     /* 16384 */
#define G3   (3*ND)      /* 3072  */
#define GRU_BLOCKS 128   /* 8 hidden columns per block */

#define IDX_OFF  ((size_t)ROWS*ND)       /* 16777216 */
#define LOSS_OFF (IDX_OFF + (size_t)ROWS)/* 16793600 */

/* ------------ scratch (static device memory: allocation-free) ------------ */
__device__ float g_hs[(size_t)ROWS*ND];    /*  64 MB  context_hidden  */
__device__ float g_cproj[(size_t)ROWS*ND]; /*  64 MB  context_proj    */
__device__ float g_gicb[(size_t)NCB*G3];   /*   3 MB  codebook@W_ih^T+b */
__device__ int   g_idx[ROWS];
__device__ float g_cn[NCB];                /* 0.5*||codebook_j||^2    */
__device__ float g_pos[NB];
__device__ float g_neg;
__device__ float g_sq;
__device__ int          g_bar_count;
__device__ volatile int g_bar_phase;

/* --------------------------- f32x2 helpers -------------------------------- */
typedef unsigned long long ull;
__device__ __forceinline__ ull ffma2(ull a, ull b, ull c) {
    ull d;
    asm("fma.rn.f32x2 %0, %1, %2, %3;" : "=l"(d) : "l"(a), "l"(b), "l"(c));
    return d;
}
__device__ __forceinline__ ull dup2(float x) {
    ull d; asm("mov.b64 %0, {%1, %1};" : "=l"(d) : "f"(x)); return d;
}
__device__ __forceinline__ float2 unpk(ull v) {
    float2 r; asm("mov.b64 {%0, %1}, %2;" : "=f"(r.x), "=f"(r.y) : "l"(v)); return r;
}

/* ------------------------------- init ----------------------------------- */
__global__ void k_init(const float* __restrict__ cb) {
    int j = blockIdx.x;
    int tid = threadIdx.x;
    const float* row = cb + (size_t)j * ND;
    float s = 0.f;
    for (int v = tid; v < ND; v += 256) { float x = row[v]; s += x * x; }
    #pragma unroll
    for (int o = 16; o; o >>= 1) s += __shfl_down_sync(0xffffffffu, s, o);
    __shared__ float red[8];
    if ((tid & 31) == 0) red[tid >> 5] = s;
    __syncthreads();
    if (tid == 0) { float t = 0.f; for (int w = 0; w < 8; w++) t += red[w]; g_cn[j] = 0.5f * t; }
    if (j == 0) {
        if (tid < NB) g_pos[tid] = 0.f;
        if (tid == 32) g_neg = 0.f;
        if (tid == 33) g_sq = 0.f;
        if (tid == 34) g_bar_count = 0;
        if (tid == 35) g_bar_phase = 0;
    }
}

/* ----------------------------- quantize ---------------------------------- */
__global__ __launch_bounds__(256) void k_quant(const float* __restrict__ feat,
                                               const float* __restrict__ cb,
                                               float* __restrict__ outq,
                                               float* __restrict__ outidx) {
    __shared__ __align__(16) float cS[NCB * 36]; /* codebook tile; reused for scores */
    __shared__ __align__(16) float fS[32 * 32];
    __shared__ int   bestS[32];
    __shared__ float redS[8];
    int tid = threadIdx.x;
    int row0 = blockIdx.x * 32;

    ull acc2[32];
    #pragma unroll
    for (int m = 0; m < 32; m++) acc2[m] = 0ull;

    for (int kb = 0; kb < ND; kb += 32) {
        { /* feature tile 32x32 */
            int fr = tid >> 3, fk = (tid & 7) * 4;
            *(float4*)&fS[fr * 32 + fk] =
                *(const float4*)&feat[(size_t)(row0 + fr) * ND + kb + fk];
        }
        #pragma unroll
        for (int v = 0; v < 8; v++) { /* codebook tile 256x32 */
            int li = tid + 256 * v;
            int cr = li >> 3, ck = (li & 7) * 4;
            *(float4*)&cS[cr * 36 + ck] =
                *(const float4*)&cb[(size_t)cr * ND + kb + ck];
        }
        __syncthreads();
        #pragma unroll
        for (int kk = 0; kk < 32; kk += 4) {
            ulonglong2 c2 = *(const ulonglong2*)&cS[tid * 36 + kk];
            #pragma unroll
            for (int m = 0; m < 32; m++) {
                ulonglong2 f2 = *(const ulonglong2*)&fS[m * 32 + kk];
                acc2[m] = ffma2(f2.x, c2.x, acc2[m]);
                acc2[m] = ffma2(f2.y, c2.y, acc2[m]);
            }
        }
        __syncthreads();
    }

    float half_cn = g_cn[tid];
    #pragma unroll
    for (int m = 0; m < 32; m++) {
        float2 p = unpk(acc2[m]);
        cS[m * 256 + tid] = half_cn - (p.x + p.y);
    }
    __syncthreads();

    int w = tid >> 5, lane = tid & 31;
    for (int mi = 0; mi < 4; mi++) {
        int m = w * 4 + mi;
        float bv = 3.0e38f; int bi = 0;
        #pragma unroll
        for (int j = 0; j < 8; j++) {
            int c = lane + 32 * j;
            float v = cS[m * 256 + c];
            if (v < bv) { bv = v; bi = c; }
        }
        #pragma unroll
        for (int o = 16; o; o >>= 1) {
            float v2 = __shfl_down_sync(0xffffffffu, bv, o);
            int   i2 = __shfl_down_sync(0xffffffffu, bi, o);
            if (v2 < bv || (v2 == bv && i2 < bi)) { bv = v2; bi = i2; }
        }
        if (lane == 0) bestS[m] = bi;
    }
    __syncthreads();

    if (tid < 32) {
        outidx[row0 + tid] = (float)bestS[tid];
        g_idx[row0 + tid] = bestS[tid];
    }

    float sq = 0.f;
    #pragma unroll 4
    for (int v = 0; v < 32; v++) {
        int i4 = tid + 256 * v;
        int m = i4 >> 8;
        int kp = (i4 & 255) * 4;
        float4 q4 = *(const float4*)&cb[(size_t)bestS[m] * ND + kp];
        float4 f4v = *(const float4*)&feat[(size_t)(row0 + m) * ND + kp];
        *(float4*)&outq[(size_t)(row0 + m) * ND + kp] = q4;
        float dx = f4v.x - q4.x, dy = f4v.y - q4.y, dz = f4v.z - q4.z, dw = f4v.w - q4.w;
        sq += dx * dx + dy * dy + dz * dz + dw * dw;
    }
    #pragma unroll
    for (int o = 16; o; o >>= 1) sq += __shfl_down_sync(0xffffffffu, sq, o);
    if (lane == 0) redS[w] = sq;
    __syncthreads();
    if (tid == 0) { float t = 0.f; for (int i = 0; i < 8; i++) t += redS[i]; atomicAdd(&g_sq, t); }
}

/* ------------------------------ SGEMM (f32x2) ----------------------------- */
/* C[M,N] = A[M,K] * Bm[N,K]^T + bias[N].  BM=128 BN=64 BK=16, 8x4/thread.  */
__global__ __launch_bounds__(256) void k_sgemm(const float* __restrict__ Aext, int a_sel,
                                               const float* __restrict__ Bm,
                                               const float* __restrict__ bias,
                                               int c_sel, int M, int N, int K) {
    const float* A = (a_sel == 0) ? Aext : g_hs;
    float* C = (c_sel == 0) ? g_gicb : g_cproj;

    __shared__ __align__(16) float As[16 * 132];
    __shared__ __align__(16) float Bs[16 * 68];
    int tid = threadIdx.x;
    int tx = tid & 15, ty = tid >> 4;
    int nbase = blockIdx.x * 64, mbase = blockIdx.y * 128;

    ull acc2[4][4];  /* row-pairs x 4 cols */
    #pragma unroll
    for (int i = 0; i < 4; i++)
        #pragma unroll
        for (int j = 0; j < 4; j++) acc2[i][j] = 0ull;

    for (int kb = 0; kb < K; kb += 16) {
        #pragma unroll
        for (int v = 0; v < 2; v++) {
            int li = tid + 256 * v;
            int ar = li >> 2, ak = (li & 3) * 4;
            float4 a = *(const float4*)&A[(size_t)(mbase + ar) * K + kb + ak];
            As[(ak + 0) * 132 + ar] = a.x; As[(ak + 1) * 132 + ar] = a.y;
            As[(ak + 2) * 132 + ar] = a.z; As[(ak + 3) * 132 + ar] = a.w;
        }
        {
            int br = tid >> 2, bk = (tid & 3) * 4;
            float4 b = *(const float4*)&Bm[(size_t)(nbase + br) * K + kb + bk];
            Bs[(bk + 0) * 68 + br] = b.x; Bs[(bk + 1) * 68 + br] = b.y;
            Bs[(bk + 2) * 68 + br] = b.z; Bs[(bk + 3) * 68 + br] = b.w;
        }
        __syncthreads();
        #pragma unroll
        for (int kk = 0; kk < 16; kk++) {
            ulonglong2 aL = *(const ulonglong2*)&As[kk * 132 + ty * 8];
            ulonglong2 aH = *(const ulonglong2*)&As[kk * 132 + ty * 8 + 4];
            float4 b0 = *(const float4*)&Bs[kk * 68 + tx * 4];
            ull bd0 = dup2(b0.x), bd1 = dup2(b0.y), bd2 = dup2(b0.z), bd3 = dup2(b0.w);
            acc2[0][0] = ffma2(aL.x, bd0, acc2[0][0]);
            acc2[0][1] = ffma2(aL.x, bd1, acc2[0][1]);
            acc2[0][2] = ffma2(aL.x, bd2, acc2[0][2]);
            acc2[0][3] = ffma2(aL.x, bd3, acc2[0][3]);
            acc2[1][0] = ffma2(aL.y, bd0, acc2[1][0]);
            acc2[1][1] = ffma2(aL.y, bd1, acc2[1][1]);
            acc2[1][2] = ffma2(aL.y, bd2, acc2[1][2]);
            acc2[1][3] = ffma2(aL.y, bd3, acc2[1][3]);
            acc2[2][0] = ffma2(aH.x, bd0, acc2[2][0]);
            acc2[2][1] = ffma2(aH.x, bd1, acc2[2][1]);
            acc2[2][2] = ffma2(aH.x, bd2, acc2[2][2]);
            acc2[2][3] = ffma2(aH.x, bd3, acc2[2][3]);
            acc2[3][0] = ffma2(aH.y, bd0, acc2[3][0]);
            acc2[3][1] = ffma2(aH.y, bd1, acc2[3][1]);
            acc2[3][2] = ffma2(aH.y, bd2, acc2[3][2]);
            acc2[3][3] = ffma2(aH.y, bd3, acc2[3][3]);
        }
        __syncthreads();
    }
    float4 bb = *(const float4*)&bias[nbase + tx * 4];
    #pragma unroll
    for (int i2 = 0; i2 < 4; i2++) {
        float2 p0 = unpk(acc2[i2][0]);
        float2 p1 = unpk(acc2[i2][1]);
        float2 p2 = unpk(acc2[i2][2]);
        float2 p3 = unpk(acc2[i2][3]);
        float4 o0, o1;
        o0.x = p0.x + bb.x; o0.y = p1.x + bb.y; o0.z = p2.x + bb.z; o0.w = p3.x + bb.w;
        o1.x = p0.y + bb.x; o1.y = p1.y + bb.y; o1.z = p2.y + bb.z; o1.w = p3.y + bb.w;
        *(float4*)&C[(size_t)(mbase + ty * 8 + 2 * i2    ) * N + nbase + tx * 4] = o0;
        *(float4*)&C[(size_t)(mbase + ty * 8 + 2 * i2 + 1) * N + nbase + tx * 4] = o1;
    }
}

/* ------------------------- persistent GRU --------------------------------- */
/* 128 blocks x 512 threads (16 warps, 4/SMSP). Block owns 8 hidden cols
   (24 W rows) resident in smem. Warp w owns k-slice [w*64, w*64+64) and
   stages exactly that slice of h_{t-1} (32 b x 64 k = 8 KB) into its private
   smem region with cp.async.cg, waiting only on its own group (+syncwarp).
   lane = batch; per 16B chunk: 24 broadcast W reads serve 32 batches.
   f32x2 FMA; 16-way k-split reduced via smem; software grid barrier. */
#define GRU_THREADS 512
#define GRU_SMEM_FLOATS (24*1024 + 32*1024)
#define GRU_SMEM_BYTES  (GRU_SMEM_FLOATS*4)      /* 229376 */

__global__ __launch_bounds__(GRU_THREADS, 1) void k_gru(const float* __restrict__ Whh,
                                                        const float* __restrict__ bhh) {
    extern __shared__ float sm[];
    float* wS = sm;               /* 24 x 1024 */
    float* hS = sm + 24 * 1024;   /* 16 warp-regions x 2048 floats */
    float* red = hS;              /* 24 x 512, overlays hS between syncs */

    const int tid = threadIdx.x;
    const int w   = tid >> 5;     /* warp id 0..15 = k-slice */
    const int b   = tid & 31;     /* lane = batch row        */
    const int jbase = blockIdx.x * 8;

    /* ---- stage W_hh tile once (6144 float4, 12/thread) ---- */
    #pragma unroll
    for (int v = 0; v < 12; v++) {
        int li = tid + GRU_THREADS * v;
        int r = li >> 8;                 /* 0..23 */
        int k4 = (li & 255) * 4;
        int g = r >> 3, jj = r & 7;
        *(float4*)&wS[r * 1024 + k4] =
            *(const float4*)&Whh[((size_t)(g * ND + jbase + jj)) * ND + k4];
    }

    /* epilogue identity: first 256 threads own (batch eb, column ej) */
    const bool epi = (tid < 256);
    const int eb = b;
    const int ejj = (tid >> 5) & 7;
    const int ej = jbase + ejj;
    float bR = 0.f, bZ = 0.f, bN = 0.f;
    if (epi) { bR = bhh[ej]; bZ = bhh[ND + ej]; bN = bhh[2 * ND + ej]; }

    /* staging: lane stages row b of its warp's 64-wide k-slice (16 chunks) */
    float* hW = hS + w * 2048;                 /* this warp's region */
    const int lsw = b & 15;                    /* chunk XOR swizzle  */
    const unsigned dstBase =
        (unsigned)__cvta_generic_to_shared(hW + b * 64);

    __syncthreads();

    float hp = 0.f;   /* h_{t-1}[eb][ej], register-carried */

    for (int t = 0; t < NT; t++) {
        /* prefetch gi (independent of h) */
        float gir = 0.f, giz = 0.f, gin = 0.f;
        if (epi) {
            int idxv = g_idx[eb * NT + t];
            const float* gic = g_gicb + (size_t)idxv * G3;
            gir = gic[ej]; giz = gic[ND + ej]; gin = gic[2 * ND + ej];
        }

        float ghr = 0.f, ghz = 0.f, ghn = 0.f;

        if (t > 0) {
            /* ---- warp-private staging of h_{t-1}[b][w*64 .. w*64+63] ---- */
            const float* src = g_hs + ((size_t)b * NT + (t - 1)) * ND + w * 64;
            #pragma unroll
            for (int c = 0; c < 16; c++) {
                unsigned dst = dstBase + ((unsigned)(c ^ lsw) << 4);
                asm volatile("cp.async.cg.shared.global [%0], [%1], 16;"
                             :: "r"(dst), "l"(src + c * 4) : "memory");
            }
            asm volatile("cp.async.commit_group;" ::: "memory");
            asm volatile("cp.async.wait_group 0;" ::: "memory");
            __syncwarp();

            /* ---- compute: 16 chunks x 24 rows, f32x2 ---- */
            ull acc[24];
            #pragma unroll
            for (int r = 0; r < 24; r++) acc[r] = 0ull;
            #pragma unroll 1
            for (int kc = 0; kc < 16; kc++) {
                ulonglong2 h2 = *(const ulonglong2*)&hW[b * 64 + ((kc ^ lsw) << 2)];
                const float* wp = wS + ((w * 16 + kc) << 2);
                #pragma unroll
                for (int r = 0; r < 24; r++) {
                    ulonglong2 w2 = *(const ulonglong2*)(wp + r * 1024);
                    acc[r] = ffma2(h2.x, w2.x, acc[r]);
                    acc[r] = ffma2(h2.y, w2.y, acc[r]);
                }
            }
            __syncthreads();   /* all hS reads done before red overlays it */

            #pragma unroll
            for (int r = 0; r < 24; r++) {
                float2 p = unpk(acc[r]);
                red[r * 512 + w * 32 + b] = p.x + p.y;
            }
            __syncthreads();

            if (epi) {
                float s0 = 0.f, s1 = 0.f, s2 = 0.f;
                #pragma unroll
                for (int ww = 0; ww < 16; ww++) {
                    s0 += red[(     ejj) * 512 + ww * 32 + eb];
                    s1 += red[( 8 + ejj) * 512 + ww * 32 + eb];
                    s2 += red[(16 + ejj) * 512 + ww * 32 + eb];
                }
                ghr = s0; ghz = s1; ghn = s2;
            }
        }

        /* ---- gate epilogue ---- */
        if (epi) {
            float rr = 1.0f / (1.0f + expf(-(gir + ghr + bR)));
            float zz = 1.0f / (1.0f + expf(-(giz + ghz + bZ)));
            float nn = tanhf(gin + rr * (ghn + bN));
            float hnew = (1.0f - zz) * nn + zz * hp;
            g_hs[((size_t)eb * NT + t) * ND + ej] = hnew;
            hp = hnew;
        }

        /* ---- grid barrier ---- */
        __threadfence();
        __syncthreads();
        if (tid == 0) {
            if (atomicAdd(&g_bar_count, 1) == GRU_BLOCKS - 1) {
                g_bar_count = 0;
                __threadfence();
                g_bar_phase = t + 1;
            } else {
                while (g_bar_phase <= t) { }
                __threadfence();
            }
        }
        __syncthreads();
    }
}

/* ---------------------------- CP loss ------------------------------------- */
__global__ __launch_bounds__(256) void k_cp(const float* __restrict__ feat,
                                            const int* __restrict__ perm) {
    int l = blockIdx.x;
    int k = blockIdx.y + 1;
    if (l >= NT - k) return;
    __shared__ __align__(16) float hS[32 * 68];
    __shared__ __align__(16) float nS[32 * 68];
    __shared__ __align__(16) float pS[32 * 68];
    __shared__ int permS[32];
    __shared__ float redS[8];
    int tid = threadIdx.x;
    if (tid < 32) permS[tid] = perm[(k - 1) * NB + tid];
    __syncthreads();

    int b = tid & 31;
    int ng = tid >> 5;
    int n0 = ng * 4;
    float acc0 = 0.f, acc1 = 0.f, acc2 = 0.f, acc3 = 0.f, accP = 0.f;

    for (int kb = 0; kb < ND; kb += 64) {
        #pragma unroll
        for (int v = 0; v < 2; v++) {
            int li = tid + 256 * v;
            int row = li >> 4;
            int kk4 = (li & 15) * 4;
            *(float4*)&hS[row * 68 + kk4] =
                *(const float4*)&g_cproj[((size_t)row * NT + l) * ND + kb + kk4];
            *(float4*)&pS[row * 68 + kk4] =
                *(const float4*)&feat[((size_t)row * NT + l + k) * ND + kb + kk4];
            *(float4*)&nS[row * 68 + kk4] =
                *(const float4*)&feat[((size_t)permS[row] * NT + l) * ND + kb + kk4];
        }
        __syncthreads();
        #pragma unroll
        for (int kk = 0; kk < 64; kk += 4) {
            float4 h4 = *(const float4*)&hS[b * 68 + kk];
            float4 m0 = *(const float4*)&nS[(n0 + 0) * 68 + kk];
            float4 m1 = *(const float4*)&nS[(n0 + 1) * 68 + kk];
            float4 m2 = *(const float4*)&nS[(n0 + 2) * 68 + kk];
            float4 m3 = *(const float4*)&nS[(n0 + 3) * 68 + kk];
            acc0 += h4.x * m0.x + h4.y * m0.y + h4.z * m0.z + h4.w * m0.w;
            acc1 += h4.x * m1.x + h4.y * m1.y + h4.z * m1.z + h4.w * m1.w;
            acc2 += h4.x * m2.x + h4.y * m2.y + h4.z * m2.z + h4.w * m2.w;
            acc3 += h4.x * m3.x + h4.y * m3.y + h4.z * m3.z + h4.w * m3.w;
            if (ng == 0) {
                float4 p4 = *(const float4*)&pS[b * 68 + kk];
                accP += h4.x * p4.x + h4.y * p4.y + h4.z * p4.z + h4.w * p4.w;
            }
        }
        __syncthreads();
    }

    float nl = 0.f;
    nl += -logf(1.0f - 1.0f / (1.0f + expf(-acc0)) + 1e-8f);
    nl += -logf(1.0f - 1.0f / (1.0f + expf(-acc1)) + 1e-8f);
    nl += -logf(1.0f - 1.0f / (1.0f + expf(-acc2)) + 1e-8f);
    nl += -logf(1.0f - 1.0f / (1.0f + expf(-acc3)) + 1e-8f);
    int lane = tid & 31;
    #pragma unroll
    for (int o = 16; o; o >>= 1) nl += __shfl_down_sync(0xffffffffu, nl, o);
    if (lane == 0) redS[tid >> 5] = nl;
    __syncthreads();
    if (tid == 0) { float s = 0.f; for (int i = 0; i < 8; i++) s += redS[i]; atomicAdd(&g_neg, s); }
    if (ng == 0) {
        float pl = -logf(1.0f / (1.0f + expf(-accP)) + 1e-8f);
        atomicAdd(&g_pos[b], pl);
    }
}

/* ----------------------------- finalize ----------------------------------- */
__global__ void k_final(float* __restrict__ outLoss) {
    int b = threadIdx.x;
    if (b < NB) {
        float cp = (g_pos[b] + 0.25f * g_neg / 1024.0f) / 1527.0f;   /* K*(T-K)=3*509 */
        float vq = 1.25f * g_sq / 16777216.0f;                        /* B*T*d */
        outLoss[b] = cp + vq;
    }
}

/* ------------------------------ launch ------------------------------------ */
extern "C" void kernel_launch(void* const* d_in, const int* in_sizes, int n_in,
                              void* d_out, int out_size) {
    (void)in_sizes; (void)n_in; (void)out_size;
    const float* feat  = (const float*)d_in[0];
    const float* cb    = (const float*)d_in[1];
    const float* Wih   = (const float*)d_in[2];
    const float* Whh   = (const float*)d_in[3];
    const float* bih   = (const float*)d_in[4];
    const float* bhh   = (const float*)d_in[5];
    const float* Wproj = (const float*)d_in[6];
    const float* bproj = (const float*)d_in[7];
    const int*   perm  = (const int*)d_in[8];

    float* out     = (float*)d_out;
    float* outq    = out;                 /* quantized (B,T,d) */
    float* outidx  = out + IDX_OFF;       /* indices as float   */
    float* outloss = out + LOSS_OFF;      /* total_loss (B,)    */

    cudaFuncSetAttribute(k_gru, cudaFuncAttributeMaxDynamicSharedMemorySize,
                         GRU_SMEM_BYTES);

    k_init<<<NCB, 256>>>(cb);
    k_quant<<<ROWS / 32, 256>>>(feat, cb, outq, outidx);
    /* gi table: (codebook @ W_ih^T + b_ih), 256 x 3072 */
    k_sgemm<<<dim3(G3 / 64, NCB / 128), 256>>>(cb, 0, Wih, bih, 0, NCB, G3, ND);
    /* persistent GRU over all 512 steps */
    k_gru<<<GRU_BLOCKS, GRU_THREADS, GRU_SMEM_BYTES>>>(Whh, bhh);
    /* context_proj = hs @ W_proj^T + b_proj */
    k_sgemm<<<dim3(ND / 64, ROWS / 128), 256>>>(nullptr, 1, Wproj, bproj, 1, ROWS, ND, ND);
    k_cp<<<dim3(NT - 1, 3), 256>>>(feat, perm);
    k_final<<<1, 32>>>(outloss);
}

// round 9
// speedup vs baseline: 1.0289x; 1.0289x over previous
#include <cuda_runtime.h>
#include <math.h>

#define NB   32
#define NT   512
#define ND   1024
#define NCB  256
#define ROWS (NB*NT)     /* 16384 */
#define G3   (3*ND)      /* 3072  */
#define GRU_BLOCKS 128   /* 8 hidden columns per block */

#define IDX_OFF  ((size_t)ROWS*ND)       /* 16777216 */
#define LOSS_OFF (IDX_OFF + (size_t)ROWS)/* 16793600 */

/* ------------ scratch (static device memory: allocation-free) ------------ */
__device__ float g_hs[(size_t)ROWS*ND];    /*  64 MB  context_hidden  */
__device__ float g_cproj[(size_t)ROWS*ND]; /*  64 MB  context_proj    */
__device__ float g_gicb[(size_t)NCB*G3];   /*   3 MB  codebook@W_ih^T+b */
__device__ int   g_idx[ROWS];
__device__ float g_cn[NCB];                /* 0.5*||codebook_j||^2    */
__device__ float g_pos[NB];
__device__ float g_neg;
__device__ float g_sq;
__device__ int          g_bar_count;
__device__ volatile int g_bar_phase;

/* --------------------------- f32x2 helpers -------------------------------- */
typedef unsigned long long ull;
__device__ __forceinline__ ull ffma2(ull a, ull b, ull c) {
    ull d;
    asm("fma.rn.f32x2 %0, %1, %2, %3;" : "=l"(d) : "l"(a), "l"(b), "l"(c));
    return d;
}
__device__ __forceinline__ ull dup2(float x) {
    ull d; asm("mov.b64 %0, {%1, %1};" : "=l"(d) : "f"(x)); return d;
}
__device__ __forceinline__ float2 unpk(ull v) {
    float2 r; asm("mov.b64 {%0, %1}, %2;" : "=f"(r.x), "=f"(r.y) : "l"(v)); return r;
}

/* ------------------------------- init ----------------------------------- */
__global__ void k_init(const float* __restrict__ cb) {
    int j = blockIdx.x;
    int tid = threadIdx.x;
    const float* row = cb + (size_t)j * ND;
    float s = 0.f;
    for (int v = tid; v < ND; v += 256) { float x = row[v]; s += x * x; }
    #pragma unroll
    for (int o = 16; o; o >>= 1) s += __shfl_down_sync(0xffffffffu, s, o);
    __shared__ float red[8];
    if ((tid & 31) == 0) red[tid >> 5] = s;
    __syncthreads();
    if (tid == 0) { float t = 0.f; for (int w = 0; w < 8; w++) t += red[w]; g_cn[j] = 0.5f * t; }
    if (j == 0) {
        if (tid < NB) g_pos[tid] = 0.f;
        if (tid == 32) g_neg = 0.f;
        if (tid == 33) g_sq = 0.f;
        if (tid == 34) g_bar_count = 0;
        if (tid == 35) g_bar_phase = 0;
    }
}

/* ----------------------------- quantize ---------------------------------- */
__global__ __launch_bounds__(256) void k_quant(const float* __restrict__ feat,
                                               const float* __restrict__ cb,
                                               float* __restrict__ outq,
                                               float* __restrict__ outidx) {
    __shared__ __align__(16) float cS[NCB * 36]; /* codebook tile; reused for scores */
    __shared__ __align__(16) float fS[32 * 32];
    __shared__ int   bestS[32];
    __shared__ float redS[8];
    int tid = threadIdx.x;
    int row0 = blockIdx.x * 32;

    ull acc2[32];
    #pragma unroll
    for (int m = 0; m < 32; m++) acc2[m] = 0ull;

    for (int kb = 0; kb < ND; kb += 32) {
        { /* feature tile 32x32 */
            int fr = tid >> 3, fk = (tid & 7) * 4;
            *(float4*)&fS[fr * 32 + fk] =
                *(const float4*)&feat[(size_t)(row0 + fr) * ND + kb + fk];
        }
        #pragma unroll
        for (int v = 0; v < 8; v++) { /* codebook tile 256x32 */
            int li = tid + 256 * v;
            int cr = li >> 3, ck = (li & 7) * 4;
            *(float4*)&cS[cr * 36 + ck] =
                *(const float4*)&cb[(size_t)cr * ND + kb + ck];
        }
        __syncthreads();
        #pragma unroll
        for (int kk = 0; kk < 32; kk += 4) {
            ulonglong2 c2 = *(const ulonglong2*)&cS[tid * 36 + kk];
            #pragma unroll
            for (int m = 0; m < 32; m++) {
                ulonglong2 f2 = *(const ulonglong2*)&fS[m * 32 + kk];
                acc2[m] = ffma2(f2.x, c2.x, acc2[m]);
                acc2[m] = ffma2(f2.y, c2.y, acc2[m]);
            }
        }
        __syncthreads();
    }

    float half_cn = g_cn[tid];
    #pragma unroll
    for (int m = 0; m < 32; m++) {
        float2 p = unpk(acc2[m]);
        cS[m * 256 + tid] = half_cn - (p.x + p.y);
    }
    __syncthreads();

    int w = tid >> 5, lane = tid & 31;
    for (int mi = 0; mi < 4; mi++) {
        int m = w * 4 + mi;
        float bv = 3.0e38f; int bi = 0;
        #pragma unroll
        for (int j = 0; j < 8; j++) {
            int c = lane + 32 * j;
            float v = cS[m * 256 + c];
            if (v < bv) { bv = v; bi = c; }
        }
        #pragma unroll
        for (int o = 16; o; o >>= 1) {
            float v2 = __shfl_down_sync(0xffffffffu, bv, o);
            int   i2 = __shfl_down_sync(0xffffffffu, bi, o);
            if (v2 < bv || (v2 == bv && i2 < bi)) { bv = v2; bi = i2; }
        }
        if (lane == 0) bestS[m] = bi;
    }
    __syncthreads();

    if (tid < 32) {
        outidx[row0 + tid] = (float)bestS[tid];
        g_idx[row0 + tid] = bestS[tid];
    }

    float sq = 0.f;
    #pragma unroll 4
    for (int v = 0; v < 32; v++) {
        int i4 = tid + 256 * v;
        int m = i4 >> 8;
        int kp = (i4 & 255) * 4;
        float4 q4 = *(const float4*)&cb[(size_t)bestS[m] * ND + kp];
        float4 f4v = *(const float4*)&feat[(size_t)(row0 + m) * ND + kp];
        *(float4*)&outq[(size_t)(row0 + m) * ND + kp] = q4;
        float dx = f4v.x - q4.x, dy = f4v.y - q4.y, dz = f4v.z - q4.z, dw = f4v.w - q4.w;
        sq += dx * dx + dy * dy + dz * dz + dw * dw;
    }
    #pragma unroll
    for (int o = 16; o; o >>= 1) sq += __shfl_down_sync(0xffffffffu, sq, o);
    if (lane == 0) redS[w] = sq;
    __syncthreads();
    if (tid == 0) { float t = 0.f; for (int i = 0; i < 8; i++) t += redS[i]; atomicAdd(&g_sq, t); }
}

/* ------------------------------ SGEMM (f32x2) ----------------------------- */
/* C[M,N] = A[M,K] * Bm[N,K]^T + bias[N].  BM=128 BN=64 BK=16, 8x4/thread.  */
__global__ __launch_bounds__(256) void k_sgemm(const float* __restrict__ Aext, int a_sel,
                                               const float* __restrict__ Bm,
                                               const float* __restrict__ bias,
                                               int c_sel, int M, int N, int K) {
    const float* A = (a_sel == 0) ? Aext : g_hs;
    float* C = (c_sel == 0) ? g_gicb : g_cproj;

    __shared__ __align__(16) float As[16 * 132];
    __shared__ __align__(16) float Bs[16 * 68];
    int tid = threadIdx.x;
    int tx = tid & 15, ty = tid >> 4;
    int nbase = blockIdx.x * 64, mbase = blockIdx.y * 128;

    ull acc2[4][4];  /* row-pairs x 4 cols */
    #pragma unroll
    for (int i = 0; i < 4; i++)
        #pragma unroll
        for (int j = 0; j < 4; j++) acc2[i][j] = 0ull;

    for (int kb = 0; kb < K; kb += 16) {
        #pragma unroll
        for (int v = 0; v < 2; v++) {
            int li = tid + 256 * v;
            int ar = li >> 2, ak = (li & 3) * 4;
            float4 a = *(const float4*)&A[(size_t)(mbase + ar) * K + kb + ak];
            As[(ak + 0) * 132 + ar] = a.x; As[(ak + 1) * 132 + ar] = a.y;
            As[(ak + 2) * 132 + ar] = a.z; As[(ak + 3) * 132 + ar] = a.w;
        }
        {
            int br = tid >> 2, bk = (tid & 3) * 4;
            float4 b = *(const float4*)&Bm[(size_t)(nbase + br) * K + kb + bk];
            Bs[(bk + 0) * 68 + br] = b.x; Bs[(bk + 1) * 68 + br] = b.y;
            Bs[(bk + 2) * 68 + br] = b.z; Bs[(bk + 3) * 68 + br] = b.w;
        }
        __syncthreads();
        #pragma unroll
        for (int kk = 0; kk < 16; kk++) {
            ulonglong2 aL = *(const ulonglong2*)&As[kk * 132 + ty * 8];
            ulonglong2 aH = *(const ulonglong2*)&As[kk * 132 + ty * 8 + 4];
            float4 b0 = *(const float4*)&Bs[kk * 68 + tx * 4];
            ull bd0 = dup2(b0.x), bd1 = dup2(b0.y), bd2 = dup2(b0.z), bd3 = dup2(b0.w);
            acc2[0][0] = ffma2(aL.x, bd0, acc2[0][0]);
            acc2[0][1] = ffma2(aL.x, bd1, acc2[0][1]);
            acc2[0][2] = ffma2(aL.x, bd2, acc2[0][2]);
            acc2[0][3] = ffma2(aL.x, bd3, acc2[0][3]);
            acc2[1][0] = ffma2(aL.y, bd0, acc2[1][0]);
            acc2[1][1] = ffma2(aL.y, bd1, acc2[1][1]);
            acc2[1][2] = ffma2(aL.y, bd2, acc2[1][2]);
            acc2[1][3] = ffma2(aL.y, bd3, acc2[1][3]);
            acc2[2][0] = ffma2(aH.x, bd0, acc2[2][0]);
            acc2[2][1] = ffma2(aH.x, bd1, acc2[2][1]);
            acc2[2][2] = ffma2(aH.x, bd2, acc2[2][2]);
            acc2[2][3] = ffma2(aH.x, bd3, acc2[2][3]);
            acc2[3][0] = ffma2(aH.y, bd0, acc2[3][0]);
            acc2[3][1] = ffma2(aH.y, bd1, acc2[3][1]);
            acc2[3][2] = ffma2(aH.y, bd2, acc2[3][2]);
            acc2[3][3] = ffma2(aH.y, bd3, acc2[3][3]);
        }
        __syncthreads();
    }
    float4 bb = *(const float4*)&bias[nbase + tx * 4];
    #pragma unroll
    for (int i2 = 0; i2 < 4; i2++) {
        float2 p0 = unpk(acc2[i2][0]);
        float2 p1 = unpk(acc2[i2][1]);
        float2 p2 = unpk(acc2[i2][2]);
        float2 p3 = unpk(acc2[i2][3]);
        float4 o0, o1;
        o0.x = p0.x + bb.x; o0.y = p1.x + bb.y; o0.z = p2.x + bb.z; o0.w = p3.x + bb.w;
        o1.x = p0.y + bb.x; o1.y = p1.y + bb.y; o1.z = p2.y + bb.z; o1.w = p3.y + bb.w;
        *(float4*)&C[(size_t)(mbase + ty * 8 + 2 * i2    ) * N + nbase + tx * 4] = o0;
        *(float4*)&C[(size_t)(mbase + ty * 8 + 2 * i2 + 1) * N + nbase + tx * 4] = o1;
    }
}

/* ------------------------- persistent GRU --------------------------------- */
/* 128 blocks x 512 threads (16 warps, 4/SMSP). Block owns 8 hidden cols
   (24 W rows) resident in smem. Warp w owns k-slice [w*64, w*64+64).
   h_{t-1} is read DIRECTLY from GMEM through L1: each lane touches 256 B
   contiguous (2 lines, fully used), 14/16 chunk loads are L1 hits. No h
   staging, no stage syncs. lane = batch; 24 broadcast W smem reads per 16B
   chunk serve all 32 batches. f32x2 FMA; 16-way k-split reduced via a
   dedicated smem region; software grid barrier per step. */
#define GRU_THREADS 512
#define GRU_SMEM_FLOATS (24*1024 + 24*512)
#define GRU_SMEM_BYTES  (GRU_SMEM_FLOATS*4)      /* 147456 */

__global__ __launch_bounds__(GRU_THREADS, 1) void k_gru(const float* __restrict__ Whh,
                                                        const float* __restrict__ bhh) {
    extern __shared__ float sm[];
    float* wS  = sm;              /* 24 x 1024 */
    float* red = sm + 24 * 1024;  /* 24 x 512  */

    const int tid = threadIdx.x;
    const int w   = tid >> 5;     /* warp id 0..15 = k-slice */
    const int b   = tid & 31;     /* lane = batch row        */
    const int jbase = blockIdx.x * 8;

    /* ---- stage W_hh tile once (6144 float4, 12/thread) ---- */
    #pragma unroll
    for (int v = 0; v < 12; v++) {
        int li = tid + GRU_THREADS * v;
        int r = li >> 8;                 /* 0..23 */
        int k4 = (li & 255) * 4;
        int g = r >> 3, jj = r & 7;
        *(float4*)&wS[r * 1024 + k4] =
            *(const float4*)&Whh[((size_t)(g * ND + jbase + jj)) * ND + k4];
    }

    /* epilogue identity: first 256 threads own (batch eb, column ej) */
    const bool epi = (tid < 256);
    const int eb = b;
    const int ejj = (tid >> 5) & 7;
    const int ej = jbase + ejj;
    float bR = 0.f, bZ = 0.f, bN = 0.f;
    if (epi) { bR = bhh[ej]; bZ = bhh[ND + ej]; bN = bhh[2 * ND + ej]; }

    /* this thread's h-slice base: batch b, k-range [w*64, w*64+64) */
    const float* hsrc0 = g_hs + (size_t)b * NT * ND + w * 64;

    __syncthreads();

    float hp = 0.f;   /* h_{t-1}[eb][ej], register-carried */

    for (int t = 0; t < NT; t++) {
        /* prefetch gi (independent of h) */
        float gir = 0.f, giz = 0.f, gin = 0.f;
        if (epi) {
            int idxv = g_idx[eb * NT + t];
            const float* gic = g_gicb + (size_t)idxv * G3;
            gir = gic[ej]; giz = gic[ND + ej]; gin = gic[2 * ND + ej];
        }

        float ghr = 0.f, ghz = 0.f, ghn = 0.f;

        if (t > 0) {
            const float* hsrc = hsrc0 + (size_t)(t - 1) * ND;

            ull acc[24];
            #pragma unroll
            for (int r = 0; r < 24; r++) acc[r] = 0ull;

            /* software-pipelined chunk loads from GMEM (L1-resident lines) */
            ulonglong2 cur = *(const ulonglong2*)(hsrc);
            #pragma unroll 1
            for (int kc = 0; kc < 16; kc++) {
                ulonglong2 nxt;
                if (kc < 15) nxt = *(const ulonglong2*)(hsrc + (kc + 1) * 4);
                const float* wp = wS + ((w * 16 + kc) << 2);
                #pragma unroll
                for (int r = 0; r < 24; r++) {
                    ulonglong2 w2 = *(const ulonglong2*)(wp + r * 1024);
                    acc[r] = ffma2(cur.x, w2.x, acc[r]);
                    acc[r] = ffma2(cur.y, w2.y, acc[r]);
                }
                cur = nxt;
            }

            #pragma unroll
            for (int r = 0; r < 24; r++) {
                float2 p = unpk(acc[r]);
                red[r * 512 + w * 32 + b] = p.x + p.y;
            }
            __syncthreads();

            if (epi) {
                float s0 = 0.f, s1 = 0.f, s2 = 0.f;
                #pragma unroll
                for (int ww = 0; ww < 16; ww++) {
                    s0 += red[(     ejj) * 512 + ww * 32 + eb];
                    s1 += red[( 8 + ejj) * 512 + ww * 32 + eb];
                    s2 += red[(16 + ejj) * 512 + ww * 32 + eb];
                }
                ghr = s0; ghz = s1; ghn = s2;
            }
        }

        /* ---- gate epilogue ---- */
        if (epi) {
            float rr = 1.0f / (1.0f + expf(-(gir + ghr + bR)));
            float zz = 1.0f / (1.0f + expf(-(giz + ghz + bZ)));
            float nn = tanhf(gin + rr * (ghn + bN));
            float hnew = (1.0f - zz) * nn + zz * hp;
            g_hs[((size_t)eb * NT + t) * ND + ej] = hnew;
            hp = hnew;
        }

        /* ---- grid barrier ---- */
        __threadfence();
        __syncthreads();
        if (tid == 0) {
            if (atomicAdd(&g_bar_count, 1) == GRU_BLOCKS - 1) {
                g_bar_count = 0;
                __threadfence();
                g_bar_phase = t + 1;
            } else {
                while (g_bar_phase <= t) { }
                __threadfence();
            }
        }
        __syncthreads();
    }
}

/* ---------------------------- CP loss ------------------------------------- */
__global__ __launch_bounds__(256) void k_cp(const float* __restrict__ feat,
                                            const int* __restrict__ perm) {
    int l = blockIdx.x;
    int k = blockIdx.y + 1;
    if (l >= NT - k) return;
    __shared__ __align__(16) float hS[32 * 68];
    __shared__ __align__(16) float nS[32 * 68];
    __shared__ __align__(16) float pS[32 * 68];
    __shared__ int permS[32];
    __shared__ float redS[8];
    int tid = threadIdx.x;
    if (tid < 32) permS[tid] = perm[(k - 1) * NB + tid];
    __syncthreads();

    int b = tid & 31;
    int ng = tid >> 5;
    int n0 = ng * 4;
    float acc0 = 0.f, acc1 = 0.f, acc2 = 0.f, acc3 = 0.f, accP = 0.f;

    for (int kb = 0; kb < ND; kb += 64) {
        #pragma unroll
        for (int v = 0; v < 2; v++) {
            int li = tid + 256 * v;
            int row = li >> 4;
            int kk4 = (li & 15) * 4;
            *(float4*)&hS[row * 68 + kk4] =
                *(const float4*)&g_cproj[((size_t)row * NT + l) * ND + kb + kk4];
            *(float4*)&pS[row * 68 + kk4] =
                *(const float4*)&feat[((size_t)row * NT + l + k) * ND + kb + kk4];
            *(float4*)&nS[row * 68 + kk4] =
                *(const float4*)&feat[((size_t)permS[row] * NT + l) * ND + kb + kk4];
        }
        __syncthreads();
        #pragma unroll
        for (int kk = 0; kk < 64; kk += 4) {
            float4 h4 = *(const float4*)&hS[b * 68 + kk];
            float4 m0 = *(const float4*)&nS[(n0 + 0) * 68 + kk];
            float4 m1 = *(const float4*)&nS[(n0 + 1) * 68 + kk];
            float4 m2 = *(const float4*)&nS[(n0 + 2) * 68 + kk];
            float4 m3 = *(const float4*)&nS[(n0 + 3) * 68 + kk];
            acc0 += h4.x * m0.x + h4.y * m0.y + h4.z * m0.z + h4.w * m0.w;
            acc1 += h4.x * m1.x + h4.y * m1.y + h4.z * m1.z + h4.w * m1.w;
            acc2 += h4.x * m2.x + h4.y * m2.y + h4.z * m2.z + h4.w * m2.w;
            acc3 += h4.x * m3.x + h4.y * m3.y + h4.z * m3.z + h4.w * m3.w;
            if (ng == 0) {
                float4 p4 = *(const float4*)&pS[b * 68 + kk];
                accP += h4.x * p4.x + h4.y * p4.y + h4.z * p4.z + h4.w * p4.w;
            }
        }
        __syncthreads();
    }

    float nl = 0.f;
    nl += -logf(1.0f - 1.0f / (1.0f + expf(-acc0)) + 1e-8f);
    nl += -logf(1.0f - 1.0f / (1.0f + expf(-acc1)) + 1e-8f);
    nl += -logf(1.0f - 1.0f / (1.0f + expf(-acc2)) + 1e-8f);
    nl += -logf(1.0f - 1.0f / (1.0f + expf(-acc3)) + 1e-8f);
    int lane = tid & 31;
    #pragma unroll
    for (int o = 16; o; o >>= 1) nl += __shfl_down_sync(0xffffffffu, nl, o);
    if (lane == 0) redS[tid >> 5] = nl;
    __syncthreads();
    if (tid == 0) { float s = 0.f; for (int i = 0; i < 8; i++) s += redS[i]; atomicAdd(&g_neg, s); }
    if (ng == 0) {
        float pl = -logf(1.0f / (1.0f + expf(-accP)) + 1e-8f);
        atomicAdd(&g_pos[b], pl);
    }
}

/* ----------------------------- finalize ----------------------------------- */
__global__ void k_final(float* __restrict__ outLoss) {
    int b = threadIdx.x;
    if (b < NB) {
        float cp = (g_pos[b] + 0.25f * g_neg / 1024.0f) / 1527.0f;   /* K*(T-K)=3*509 */
        float vq = 1.25f * g_sq / 16777216.0f;                        /* B*T*d */
        outLoss[b] = cp + vq;
    }
}

/* ------------------------------ launch ------------------------------------ */
extern "C" void kernel_launch(void* const* d_in, const int* in_sizes, int n_in,
                              void* d_out, int out_size) {
    (void)in_sizes; (void)n_in; (void)out_size;
    const float* feat  = (const float*)d_in[0];
    const float* cb    = (const float*)d_in[1];
    const float* Wih   = (const float*)d_in[2];
    const float* Whh   = (const float*)d_in[3];
    const float* bih   = (const float*)d_in[4];
    const float* bhh   = (const float*)d_in[5];
    const float* Wproj = (const float*)d_in[6];
    const float* bproj = (const float*)d_in[7];
    const int*   perm  = (const int*)d_in[8];

    float* out     = (float*)d_out;
    float* outq    = out;                 /* quantized (B,T,d) */
    float* outidx  = out + IDX_OFF;       /* indices as float   */
    float* outloss = out + LOSS_OFF;      /* total_loss (B,)    */

    cudaFuncSetAttribute(k_gru, cudaFuncAttributeMaxDynamicSharedMemorySize,
                         GRU_SMEM_BYTES);

    k_init<<<NCB, 256>>>(cb);
    k_quant<<<ROWS / 32, 256>>>(feat, cb, outq, outidx);
    /* gi table: (codebook @ W_ih^T + b_ih), 256 x 3072 */
    k_sgemm<<<dim3(G3 / 64, NCB / 128), 256>>>(cb, 0, Wih, bih, 0, NCB, G3, ND);
    /* persistent GRU over all 512 steps */
    k_gru<<<GRU_BLOCKS, GRU_THREADS, GRU_SMEM_BYTES>>>(Whh, bhh);
    /* context_proj = hs @ W_proj^T + b_proj */
    k_sgemm<<<dim3(ND / 64, ROWS / 128), 256>>>(nullptr, 1, Wproj, bproj, 1, ROWS, ND, ND);
    k_cp<<<dim3(NT - 1, 3), 256>>>(feat, perm);
    k_final<<<1, 32>>>(outloss);
}

// round 11
// speedup vs baseline: 1.2966x; 1.2602x over previous
#include <cuda_runtime.h>
#include <math.h>

#define NB   32
#define NT   512
#define ND   1024
#define NCB  256
#define ROWS (NB*NT)     /* 16384 */
#define G3   (3*ND)      /* 3072  */
#define GRU_BLOCKS 128   /* 8 hidden columns per block */
#define HSTRIDE 1036     /* padded h row stride (floats), conflict-free */

#define IDX_OFF  ((size_t)ROWS*ND)       /* 16777216 */
#define LOSS_OFF (IDX_OFF + (size_t)ROWS)/* 16793600 */

/* ------------ scratch (static device memory: allocation-free) ------------ */
__device__ float g_hs[(size_t)ROWS*ND];    /*  64 MB  context_hidden  */
__device__ float g_cproj[(size_t)ROWS*ND]; /*  64 MB  context_proj    */
__device__ float g_gicb[(size_t)NCB*G3];   /*   3 MB  codebook@W_ih^T+b */
__device__ int   g_idx[ROWS];
__device__ float g_cn[NCB];                /* 0.5*||codebook_j||^2    */
__device__ float g_pos[NB];
__device__ float g_neg;
__device__ float g_sq;
__device__ int          g_cnt[256];        /* 8 spread group counters  */
__device__ int          g_root;
__device__ volatile int g_bar_phase;

/* --------------------------- f32x2 helpers -------------------------------- */
typedef unsigned long long ull;
__device__ __forceinline__ ull ffma2(ull a, ull b, ull c) {
    ull d;
    asm("fma.rn.f32x2 %0, %1, %2, %3;" : "=l"(d) : "l"(a), "l"(b), "l"(c));
    return d;
}
__device__ __forceinline__ ull dup2(float x) {
    ull d; asm("mov.b64 %0, {%1, %1};" : "=l"(d) : "f"(x)); return d;
}
__device__ __forceinline__ float2 unpk(ull v) {
    float2 r; asm("mov.b64 {%0, %1}, %2;" : "=f"(r.x), "=f"(r.y) : "l"(v)); return r;
}

/* ------------------------------- init ----------------------------------- */
__global__ void k_init(const float* __restrict__ cb) {
    int j = blockIdx.x;
    int tid = threadIdx.x;
    const float* row = cb + (size_t)j * ND;
    float s = 0.f;
    for (int v = tid; v < ND; v += 256) { float x = row[v]; s += x * x; }
    #pragma unroll
    for (int o = 16; o; o >>= 1) s += __shfl_down_sync(0xffffffffu, s, o);
    __shared__ float red[8];
    if ((tid & 31) == 0) red[tid >> 5] = s;
    __syncthreads();
    if (tid == 0) { float t = 0.f; for (int w = 0; w < 8; w++) t += red[w]; g_cn[j] = 0.5f * t; }
    if (j == 0) {
        g_cnt[tid] = 0;
        if (tid < NB) g_pos[tid] = 0.f;
        if (tid == 32) g_neg = 0.f;
        if (tid == 33) g_sq = 0.f;
        if (tid == 34) g_root = 0;
        if (tid == 35) g_bar_phase = 0;
    }
}

/* ----------------------------- quantize ---------------------------------- */
__global__ __launch_bounds__(256) void k_quant(const float* __restrict__ feat,
                                               const float* __restrict__ cb,
                                               float* __restrict__ outq,
                                               float* __restrict__ outidx) {
    __shared__ __align__(16) float cS[NCB * 36]; /* codebook tile; reused for scores */
    __shared__ __align__(16) float fS[32 * 32];
    __shared__ int   bestS[32];
    __shared__ float redS[8];
    int tid = threadIdx.x;
    int row0 = blockIdx.x * 32;

    ull acc2[32];
    #pragma unroll
    for (int m = 0; m < 32; m++) acc2[m] = 0ull;

    for (int kb = 0; kb < ND; kb += 32) {
        { /* feature tile 32x32 */
            int fr = tid >> 3, fk = (tid & 7) * 4;
            *(float4*)&fS[fr * 32 + fk] =
                *(const float4*)&feat[(size_t)(row0 + fr) * ND + kb + fk];
        }
        #pragma unroll
        for (int v = 0; v < 8; v++) { /* codebook tile 256x32 */
            int li = tid + 256 * v;
            int cr = li >> 3, ck = (li & 7) * 4;
            *(float4*)&cS[cr * 36 + ck] =
                *(const float4*)&cb[(size_t)cr * ND + kb + ck];
        }
        __syncthreads();
        #pragma unroll
        for (int kk = 0; kk < 32; kk += 4) {
            ulonglong2 c2 = *(const ulonglong2*)&cS[tid * 36 + kk];
            #pragma unroll
            for (int m = 0; m < 32; m++) {
                ulonglong2 f2 = *(const ulonglong2*)&fS[m * 32 + kk];
                acc2[m] = ffma2(f2.x, c2.x, acc2[m]);
                acc2[m] = ffma2(f2.y, c2.y, acc2[m]);
            }
        }
        __syncthreads();
    }

    float half_cn = g_cn[tid];
    #pragma unroll
    for (int m = 0; m < 32; m++) {
        float2 p = unpk(acc2[m]);
        cS[m * 256 + tid] = half_cn - (p.x + p.y);
    }
    __syncthreads();

    int w = tid >> 5, lane = tid & 31;
    for (int mi = 0; mi < 4; mi++) {
        int m = w * 4 + mi;
        float bv = 3.0e38f; int bi = 0;
        #pragma unroll
        for (int j = 0; j < 8; j++) {
            int c = lane + 32 * j;
            float v = cS[m * 256 + c];
            if (v < bv) { bv = v; bi = c; }
        }
        #pragma unroll
        for (int o = 16; o; o >>= 1) {
            float v2 = __shfl_down_sync(0xffffffffu, bv, o);
            int   i2 = __shfl_down_sync(0xffffffffu, bi, o);
            if (v2 < bv || (v2 == bv && i2 < bi)) { bv = v2; bi = i2; }
        }
        if (lane == 0) bestS[m] = bi;
    }
    __syncthreads();

    if (tid < 32) {
        outidx[row0 + tid] = (float)bestS[tid];
        g_idx[row0 + tid] = bestS[tid];
    }

    float sq = 0.f;
    #pragma unroll 4
    for (int v = 0; v < 32; v++) {
        int i4 = tid + 256 * v;
        int m = i4 >> 8;
        int kp = (i4 & 255) * 4;
        float4 q4 = *(const float4*)&cb[(size_t)bestS[m] * ND + kp];
        float4 f4v = *(const float4*)&feat[(size_t)(row0 + m) * ND + kp];
        *(float4*)&outq[(size_t)(row0 + m) * ND + kp] = q4;
        float dx = f4v.x - q4.x, dy = f4v.y - q4.y, dz = f4v.z - q4.z, dw = f4v.w - q4.w;
        sq += dx * dx + dy * dy + dz * dz + dw * dw;
    }
    #pragma unroll
    for (int o = 16; o; o >>= 1) sq += __shfl_down_sync(0xffffffffu, sq, o);
    if (lane == 0) redS[w] = sq;
    __syncthreads();
    if (tid == 0) { float t = 0.f; for (int i = 0; i < 8; i++) t += redS[i]; atomicAdd(&g_sq, t); }
}

/* ------------------------------ SGEMM (f32x2) ----------------------------- */
__global__ __launch_bounds__(256) void k_sgemm(const float* __restrict__ Aext, int a_sel,
                                               const float* __restrict__ Bm,
                                               const float* __restrict__ bias,
                                               int c_sel, int M, int N, int K) {
    const float* A = (a_sel == 0) ? Aext : g_hs;
    float* C = (c_sel == 0) ? g_gicb : g_cproj;

    __shared__ __align__(16) float As[16 * 132];
    __shared__ __align__(16) float Bs[16 * 68];
    int tid = threadIdx.x;
    int tx = tid & 15, ty = tid >> 4;
    int nbase = blockIdx.x * 64, mbase = blockIdx.y * 128;

    ull acc2[4][4];
    #pragma unroll
    for (int i = 0; i < 4; i++)
        #pragma unroll
        for (int j = 0; j < 4; j++) acc2[i][j] = 0ull;

    for (int kb = 0; kb < K; kb += 16) {
        #pragma unroll
        for (int v = 0; v < 2; v++) {
            int li = tid + 256 * v;
            int ar = li >> 2, ak = (li & 3) * 4;
            float4 a = *(const float4*)&A[(size_t)(mbase + ar) * K + kb + ak];
            As[(ak + 0) * 132 + ar] = a.x; As[(ak + 1) * 132 + ar] = a.y;
            As[(ak + 2) * 132 + ar] = a.z; As[(ak + 3) * 132 + ar] = a.w;
        }
        {
            int br = tid >> 2, bk = (tid & 3) * 4;
            float4 b = *(const float4*)&Bm[(size_t)(nbase + br) * K + kb + bk];
            Bs[(bk + 0) * 68 + br] = b.x; Bs[(bk + 1) * 68 + br] = b.y;
            Bs[(bk + 2) * 68 + br] = b.z; Bs[(bk + 3) * 68 + br] = b.w;
        }
        __syncthreads();
        #pragma unroll
        for (int kk = 0; kk < 16; kk++) {
            ulonglong2 aL = *(const ulonglong2*)&As[kk * 132 + ty * 8];
            ulonglong2 aH = *(const ulonglong2*)&As[kk * 132 + ty * 8 + 4];
            float4 b0 = *(const float4*)&Bs[kk * 68 + tx * 4];
            ull bd0 = dup2(b0.x), bd1 = dup2(b0.y), bd2 = dup2(b0.z), bd3 = dup2(b0.w);
            acc2[0][0] = ffma2(aL.x, bd0, acc2[0][0]);
            acc2[0][1] = ffma2(aL.x, bd1, acc2[0][1]);
            acc2[0][2] = ffma2(aL.x, bd2, acc2[0][2]);
            acc2[0][3] = ffma2(aL.x, bd3, acc2[0][3]);
            acc2[1][0] = ffma2(aL.y, bd0, acc2[1][0]);
            acc2[1][1] = ffma2(aL.y, bd1, acc2[1][1]);
            acc2[1][2] = ffma2(aL.y, bd2, acc2[1][2]);
            acc2[1][3] = ffma2(aL.y, bd3, acc2[1][3]);
            acc2[2][0] = ffma2(aH.x, bd0, acc2[2][0]);
            acc2[2][1] = ffma2(aH.x, bd1, acc2[2][1]);
            acc2[2][2] = ffma2(aH.x, bd2, acc2[2][2]);
            acc2[2][3] = ffma2(aH.x, bd3, acc2[2][3]);
            acc2[3][0] = ffma2(aH.y, bd0, acc2[3][0]);
            acc2[3][1] = ffma2(aH.y, bd1, acc2[3][1]);
            acc2[3][2] = ffma2(aH.y, bd2, acc2[3][2]);
            acc2[3][3] = ffma2(aH.y, bd3, acc2[3][3]);
        }
        __syncthreads();
    }
    float4 bb = *(const float4*)&bias[nbase + tx * 4];
    #pragma unroll
    for (int i2 = 0; i2 < 4; i2++) {
        float2 p0 = unpk(acc2[i2][0]);
        float2 p1 = unpk(acc2[i2][1]);
        float2 p2 = unpk(acc2[i2][2]);
        float2 p3 = unpk(acc2[i2][3]);
        float4 o0, o1;
        o0.x = p0.x + bb.x; o0.y = p1.x + bb.y; o0.z = p2.x + bb.z; o0.w = p3.x + bb.w;
        o1.x = p0.y + bb.x; o1.y = p1.y + bb.y; o1.z = p2.y + bb.z; o1.w = p3.y + bb.w;
        *(float4*)&C[(size_t)(mbase + ty * 8 + 2 * i2    ) * N + nbase + tx * 4] = o0;
        *(float4*)&C[(size_t)(mbase + ty * 8 + 2 * i2 + 1) * N + nbase + tx * 4] = o1;
    }
}

/* ------------------------- persistent GRU --------------------------------- */
/* 128 blocks x 256 threads (8 warps, 2/SMSP). Block owns 8 hidden cols
   (24 W rows) resident in smem. Warp w owns k-slice [w*128, w*128+128).
   h_{t-1} staged block-wide COALESCED into padded smem (stride 1036).
   lane = (bg 0..15, ks 0..1): each lane accumulates 2 batches (2bg, 2bg+1)
   over its 4-float k-subword -> one W LDS.128 (2x16B distinct = 1 wavefront)
   serves 2 batches: W wavefronts halved vs broadcast-per-4-floats.
   f32x2 FMA; 16-way (8 warps x 2 ks) k-split reduced via smem; two-level
   tree grid barrier (8 spread counters x 16 + root). */
#define GRU_SMEM_FLOATS (24*1024 + 32*HSTRIDE)
#define GRU_SMEM_BYTES  (GRU_SMEM_FLOATS*4)      /* 230912 <= 232448 */

__global__ __launch_bounds__(256, 1) void k_gru(const float* __restrict__ Whh,
                                                const float* __restrict__ bhh) {
    extern __shared__ float sm[];
    float* wS = sm;                   /* 24 x 1024 */
    float* hS = sm + 24 * 1024;       /* 32 x 1036 */
    float* red = hS;                  /* 16 x 768, overlays hS after sync */

    const int tid = threadIdx.x;
    const int w   = tid >> 5;         /* warp = k-slice (128 floats) */
    const int lane = tid & 31;
    const int bg  = lane >> 1;        /* batch pair 0..15 */
    const int ks  = lane & 1;         /* k subword 0/1    */
    const int b0  = 2 * bg, b1 = 2 * bg + 1;
    const int jbase = blockIdx.x * 8;

    /* ---- stage W_hh tile once ---- */
    #pragma unroll
    for (int v = 0; v < 24; v++) {
        int li = tid + 256 * v;
        int r = li >> 8;
        int k4 = (li & 255) * 4;
        int g = r >> 3, jj = r & 7;
        *(float4*)&wS[r * 1024 + k4] =
            *(const float4*)&Whh[((size_t)(g * ND + jbase + jj)) * ND + k4];
    }

    /* epilogue identity: thread owns (batch eb, column ej) */
    const int eb = lane, ejj = w;
    const int ej = jbase + ejj;
    const float bR = bhh[ej], bZ = bhh[ND + ej], bN = bhh[2 * ND + ej];

    /* staging identity: thread (sb, skq) covers row sb, float4s skq+8i */
    const int sb = tid >> 3, skq = tid & 7;

    __syncthreads();

    float hp = 0.f;   /* h_{t-1}[eb][ej], register-carried */

    /* prefetch gi for t=0 */
    int pidx = g_idx[eb * NT + 0];
    float gir = g_gicb[(size_t)pidx * G3 + ej];
    float giz = g_gicb[(size_t)pidx * G3 + ND + ej];
    float gin = g_gicb[(size_t)pidx * G3 + 2 * ND + ej];

    for (int t = 0; t < NT; t++) {
        float ghr = 0.f, ghz = 0.f, ghn = 0.f;

        if (t > 0) {
            /* ---- coalesced staging of h_{t-1} ---- */
            const float* src = g_hs + ((size_t)sb * NT + (t - 1)) * ND;
            float* dst = hS + sb * HSTRIDE;
            #pragma unroll 8
            for (int i = 0; i < 32; i++) {
                int c = skq + 8 * i;
                float4 v = __ldcg((const float4*)(src + c * 4));
                *(float4*)&dst[c * 4] = v;
            }
            __syncthreads();

            /* ---- compute: 16 chunks of 8 floats; lane handles its 4 ---- */
            ull accA[24], accB[24];
            #pragma unroll
            for (int r = 0; r < 24; r++) { accA[r] = 0ull; accB[r] = 0ull; }
            const int obase = w * 128 + ks * 4;
            #pragma unroll 1
            for (int c = 0; c < 16; c++) {
                const int off = obase + c * 8;
                ulonglong2 ha = *(const ulonglong2*)&hS[b0 * HSTRIDE + off];
                ulonglong2 hb = *(const ulonglong2*)&hS[b1 * HSTRIDE + off];
                const float* wp = wS + off;
                #pragma unroll
                for (int r = 0; r < 24; r++) {
                    ulonglong2 w2 = *(const ulonglong2*)(wp + r * 1024);
                    accA[r] = ffma2(ha.x, w2.x, accA[r]);
                    accA[r] = ffma2(ha.y, w2.y, accA[r]);
                    accB[r] = ffma2(hb.x, w2.x, accB[r]);
                    accB[r] = ffma2(hb.y, w2.y, accB[r]);
                }
            }
            __syncthreads();   /* hS reads done before red overlays it */

            /* partials: red[(w*2+ks)*768 + r*32 + b] (float2 per pair) */
            {
                float* rb = red + (w * 2 + ks) * 768;
                #pragma unroll
                for (int r = 0; r < 24; r++) {
                    float2 pa = unpk(accA[r]);
                    float2 pb = unpk(accB[r]);
                    float2 v2 = make_float2(pa.x + pa.y, pb.x + pb.y);
                    *(float2*)&rb[r * 32 + b0] = v2;
                }
            }
            __syncthreads();

            /* 16-way reduction for (row=g*8+ejj, batch=eb) */
            {
                float s0 = 0.f, s1 = 0.f, s2 = 0.f;
                const int r0 = ejj, r1 = 8 + ejj, r2 = 16 + ejj;
                #pragma unroll
                for (int i = 0; i < 16; i++) {
                    const float* rb = red + i * 768;
                    s0 += rb[r0 * 32 + eb];
                    s1 += rb[r1 * 32 + eb];
                    s2 += rb[r2 * 32 + eb];
                }
                ghr = s0; ghz = s1; ghn = s2;
            }
        }

        /* ---- gate epilogue ---- */
        {
            float rr = 1.0f / (1.0f + expf(-(gir + ghr + bR)));
            float zz = 1.0f / (1.0f + expf(-(giz + ghz + bZ)));
            float nn = tanhf(gin + rr * (ghn + bN));
            float hnew = (1.0f - zz) * nn + zz * hp;
            g_hs[((size_t)eb * NT + t) * ND + ej] = hnew;
            hp = hnew;
        }

        /* ---- two-level tree grid barrier ---- */
        __threadfence();
        __syncthreads();
        if (tid == 0) {
            int grp = blockIdx.x & 7;
            int v = atomicAdd(&g_cnt[grp * 32], 1);
            if ((v & 15) == 15) {                 /* last of 16 in group */
                int r = atomicAdd(&g_root, 1);
                if ((r & 7) == 7) {               /* last group */
                    __threadfence();
                    g_bar_phase = t + 1;
                }
            }
        }
        /* prefetch gi for t+1 while tid0 polls */
        if (t + 1 < NT) {
            int nidx = g_idx[eb * NT + t + 1];
            gir = g_gicb[(size_t)nidx * G3 + ej];
            giz = g_gicb[(size_t)nidx * G3 + ND + ej];
            gin = g_gicb[(size_t)nidx * G3 + 2 * ND + ej];
        }
        if (tid == 0) {
            while (g_bar_phase <= t) { }
            __threadfence();
        }
        __syncthreads();
    }
}

/* ---------------------------- CP loss ------------------------------------- */
__global__ __launch_bounds__(256) void k_cp(const float* __restrict__ feat,
                                            const int* __restrict__ perm) {
    int l = blockIdx.x;
    int k = blockIdx.y + 1;
    if (l >= NT - k) return;
    __shared__ __align__(16) float hS[32 * 68];
    __shared__ __align__(16) float nS[32 * 68];
    __shared__ __align__(16) float pS[32 * 68];
    __shared__ int permS[32];
    __shared__ float redS[8];
    int tid = threadIdx.x;
    if (tid < 32) permS[tid] = perm[(k - 1) * NB + tid];
    __syncthreads();

    int b = tid & 31;
    int ng = tid >> 5;
    int n0 = ng * 4;
    float acc0 = 0.f, acc1 = 0.f, acc2 = 0.f, acc3 = 0.f, accP = 0.f;

    for (int kb = 0; kb < ND; kb += 64) {
        #pragma unroll
        for (int v = 0; v < 2; v++) {
            int li = tid + 256 * v;
            int row = li >> 4;
            int kk4 = (li & 15) * 4;
            *(float4*)&hS[row * 68 + kk4] =
                *(const float4*)&g_cproj[((size_t)row * NT + l) * ND + kb + kk4];
            *(float4*)&pS[row * 68 + kk4] =
                *(const float4*)&feat[((size_t)row * NT + l + k) * ND + kb + kk4];
            *(float4*)&nS[row * 68 + kk4] =
                *(const float4*)&feat[((size_t)permS[row] * NT + l) * ND + kb + kk4];
        }
        __syncthreads();
        #pragma unroll
        for (int kk = 0; kk < 64; kk += 4) {
            float4 h4 = *(const float4*)&hS[b * 68 + kk];
            float4 m0 = *(const float4*)&nS[(n0 + 0) * 68 + kk];
            float4 m1 = *(const float4*)&nS[(n0 + 1) * 68 + kk];
            float4 m2 = *(const float4*)&nS[(n0 + 2) * 68 + kk];
            float4 m3 = *(const float4*)&nS[(n0 + 3) * 68 + kk];
            acc0 += h4.x * m0.x + h4.y * m0.y + h4.z * m0.z + h4.w * m0.w;
            acc1 += h4.x * m1.x + h4.y * m1.y + h4.z * m1.z + h4.w * m1.w;
            acc2 += h4.x * m2.x + h4.y * m2.y + h4.z * m2.z + h4.w * m2.w;
            acc3 += h4.x * m3.x + h4.y * m3.y + h4.z * m3.z + h4.w * m3.w;
            if (ng == 0) {
                float4 p4 = *(const float4*)&pS[b * 68 + kk];
                accP += h4.x * p4.x + h4.y * p4.y + h4.z * p4.z + h4.w * p4.w;
            }
        }
        __syncthreads();
    }

    float nl = 0.f;
    nl += -logf(1.0f - 1.0f / (1.0f + expf(-acc0)) + 1e-8f);
    nl += -logf(1.0f - 1.0f / (1.0f + expf(-acc1)) + 1e-8f);
    nl += -logf(1.0f - 1.0f / (1.0f + expf(-acc2)) + 1e-8f);
    nl += -logf(1.0f - 1.0f / (1.0f + expf(-acc3)) + 1e-8f);
    int lane = tid & 31;
    #pragma unroll
    for (int o = 16; o; o >>= 1) nl += __shfl_down_sync(0xffffffffu, nl, o);
    if (lane == 0) redS[tid >> 5] = nl;
    __syncthreads();
    if (tid == 0) { float s = 0.f; for (int i = 0; i < 8; i++) s += redS[i]; atomicAdd(&g_neg, s); }
    if (ng == 0) {
        float pl = -logf(1.0f / (1.0f + expf(-accP)) + 1e-8f);
        atomicAdd(&g_pos[b], pl);
    }
}

/* ----------------------------- finalize ----------------------------------- */
__global__ void k_final(float* __restrict__ outLoss) {
    int b = threadIdx.x;
    if (b < NB) {
        float cp = (g_pos[b] + 0.25f * g_neg / 1024.0f) / 1527.0f;   /* K*(T-K)=3*509 */
        float vq = 1.25f * g_sq / 16777216.0f;                        /* B*T*d */
        outLoss[b] = cp + vq;
    }
}

/* ------------------------------ launch ------------------------------------ */
extern "C" void kernel_launch(void* const* d_in, const int* in_sizes, int n_in,
                              void* d_out, int out_size) {
    (void)in_sizes; (void)n_in; (void)out_size;
    const float* feat  = (const float*)d_in[0];
    const float* cb    = (const float*)d_in[1];
    const float* Wih   = (const float*)d_in[2];
    const float* Whh   = (const float*)d_in[3];
    const float* bih   = (const float*)d_in[4];
    const float* bhh   = (const float*)d_in[5];
    const float* Wproj = (const float*)d_in[6];
    const float* bproj = (const float*)d_in[7];
    const int*   perm  = (const int*)d_in[8];

    float* out     = (float*)d_out;
    float* outq    = out;                 /* quantized (B,T,d) */
    float* outidx  = out + IDX_OFF;       /* indices as float   */
    float* outloss = out + LOSS_OFF;      /* total_loss (B,)    */

    cudaFuncSetAttribute(k_gru, cudaFuncAttributeMaxDynamicSharedMemorySize,
                         GRU_SMEM_BYTES);

    k_init<<<NCB, 256>>>(cb);
    k_quant<<<ROWS / 32, 256>>>(feat, cb, outq, outidx);
    /* gi table: (codebook @ W_ih^T + b_ih), 256 x 3072 */
    k_sgemm<<<dim3(G3 / 64, NCB / 128), 256>>>(cb, 0, Wih, bih, 0, NCB, G3, ND);
    /* persistent GRU over all 512 steps */
    k_gru<<<GRU_BLOCKS, 256, GRU_SMEM_BYTES>>>(Whh, bhh);
    /* context_proj = hs @ W_proj^T + b_proj */
    k_sgemm<<<dim3(ND / 64, ROWS / 128), 256>>>(nullptr, 1, Wproj, bproj, 1, ROWS, ND, ND);
    k_cp<<<dim3(NT - 1, 3), 256>>>(feat, perm);
    k_final<<<1, 32>>>(outloss);
}